// round 16
// baseline (speedup 1.0000x reference)
#include <cuda_runtime.h>
#include <cuda_bf16.h>
#include <math.h>
#include <stdint.h>

// NT-Xent loss, B=4096, D=256, N=8192.  bf16 HMMA Gram tiles.
// Persistent sim kernel with work-stealing + cross-tile cp.async pipeline.
//  1) normalize_kernel: zn bf16; zeros g_denom, g_ticket, out.
//  2) sim_kernel (persistent, 2/SM): triangular 128x128 tiles via mma.sync
//     bf16; 8 warps 2(M)x4(N), warp tile 64x32; K chunks of 64, cp.async
//     double buffer; chunk0 of the NEXT tile is prefetched before the
//     epilogue of the current tile. Epilogue: exp(2*sim), diag zeroed,
//     rowsum->g_denom[m], colsum->g_denom[n]; positive band -> g_pos.
//  3) loss_kernel (PDL): loss = log(denom) - 2*pos; reduce + atomicAdd.

#define DIM 256
#define MAXN 8192
#define BK 64

__device__ __nv_bfloat16 g_zn[MAXN * DIM];
__device__ float g_denom[MAXN];
__device__ float g_pos[MAXN];
__device__ int g_ticket;

__device__ __forceinline__ uint32_t smem_u32(const void* p) {
    uint32_t a;
    asm("{ .reg .u64 t; cvta.to.shared.u64 t, %1; cvt.u32.u64 %0, t; }"
        : "=r"(a) : "l"(p));
    return a;
}

__device__ __forceinline__ void ldsm_x4(uint32_t* r, uint32_t addr) {
    asm volatile("ldmatrix.sync.aligned.m8n8.x4.shared.b16 {%0,%1,%2,%3}, [%4];"
                 : "=r"(r[0]), "=r"(r[1]), "=r"(r[2]), "=r"(r[3]) : "r"(addr));
}

__device__ __forceinline__ void mma16816(float* c, const uint32_t* a,
                                         const uint32_t* b) {
    asm volatile(
        "mma.sync.aligned.m16n8k16.row.col.f32.bf16.bf16.f32 "
        "{%0,%1,%2,%3}, {%4,%5,%6,%7}, {%8,%9}, {%0,%1,%2,%3};"
        : "+f"(c[0]), "+f"(c[1]), "+f"(c[2]), "+f"(c[3])
        : "r"(a[0]), "r"(a[1]), "r"(a[2]), "r"(a[3]), "r"(b[0]), "r"(b[1]));
}

__device__ __forceinline__ void cp_async16(uint32_t saddr, uint64_t gaddr) {
    asm volatile("cp.async.cg.shared.global [%0], [%1], 16;"
                 :: "r"(saddr), "l"(gaddr) : "memory");
}
#define CP_COMMIT() asm volatile("cp.async.commit_group;" ::: "memory")
#define CP_WAIT(n)  asm volatile("cp.async.wait_group %0;" :: "n"(n) : "memory")

#define GDC_WAIT()    asm volatile("griddepcontrol.wait;" ::: "memory")
#define GDC_LAUNCH()  asm volatile("griddepcontrol.launch_dependents;")

// ---------------------------------------------------------------------------
// 1) Normalize -> bf16 (1 row/warp); zero g_denom, g_ticket, out.
// ---------------------------------------------------------------------------
__global__ void normalize_kernel(const float* __restrict__ zi,
                                 const float* __restrict__ zj,
                                 int B, int N, float* out) {
    int tid  = threadIdx.x;
    int warp = tid >> 5;
    int lane = tid & 31;
    int row  = blockIdx.x * 8 + warp;

    int gtid = blockIdx.x * blockDim.x + tid;
    if (gtid < N) g_denom[gtid] = 0.0f;
    if (gtid == 0) { out[0] = 0.0f; g_ticket = 0; }

    if (row < N) {
        const float* src = (row < B) ? (zi + (size_t)row * DIM)
                                     : (zj + (size_t)(row - B) * DIM);
        float4 v0 = *reinterpret_cast<const float4*>(src + lane * 8);
        float4 v1 = *reinterpret_cast<const float4*>(src + lane * 8 + 4);
        float ss = v0.x*v0.x + v0.y*v0.y + v0.z*v0.z + v0.w*v0.w
                 + v1.x*v1.x + v1.y*v1.y + v1.z*v1.z + v1.w*v1.w;
#pragma unroll
        for (int off = 16; off > 0; off >>= 1)
            ss += __shfl_xor_sync(0xFFFFFFFF, ss, off);
        float inv = 1.0f / fmaxf(sqrtf(ss), 1e-8f);

        __nv_bfloat16 h[8];
        h[0] = __float2bfloat16(v0.x * inv); h[1] = __float2bfloat16(v0.y * inv);
        h[2] = __float2bfloat16(v0.z * inv); h[3] = __float2bfloat16(v0.w * inv);
        h[4] = __float2bfloat16(v1.x * inv); h[5] = __float2bfloat16(v1.y * inv);
        h[6] = __float2bfloat16(v1.z * inv); h[7] = __float2bfloat16(v1.w * inv);
        *reinterpret_cast<uint4*>(g_zn + (size_t)row * DIM + lane * 8) =
            *reinterpret_cast<uint4*>(h);
    }
    GDC_LAUNCH();
}

// ---------------------------------------------------------------------------
// decode triangular linear index -> (bm, bn), bn >= bm
// ---------------------------------------------------------------------------
__device__ __forceinline__ void tri_decode(int t, int nt, int& bm, int& bn) {
    float f = 2.0f * (float)nt + 1.0f;
    bm = (int)((f - sqrtf(f * f - 8.0f * (float)t)) * 0.5f);
    while ((bm + 1) * nt - (((bm + 1) * bm) >> 1) <= t) bm++;
    while (bm * nt - ((bm * (bm - 1)) >> 1) > t) bm--;
    bn = bm + (t - (bm * nt - ((bm * (bm - 1)) >> 1)));
}

// ---------------------------------------------------------------------------
// 2) Persistent bf16 HMMA Gram kernel.
// ---------------------------------------------------------------------------
__global__ __launch_bounds__(256, 2) void sim_kernel(int nt, int btile,
                                                     int ntri) {
    extern __shared__ char dsm[];
    __shared__ float rowsum[128];
    __shared__ float colsum[128];
    __shared__ int s_next;

    int tid  = threadIdx.x;
    int wid  = tid >> 5;
    int lane = tid & 31;
    int warp_m = wid & 1;      // rows 64*warp_m
    int warp_n = wid >> 1;     // cols 32*warp_n

    uint32_t sbase = smem_u32(dsm);
    uint64_t gbase = (uint64_t)__cvta_generic_to_global(g_zn);

    int a_row = warp_m * 64 + (lane & 15);                         // + mt*16
    int a_ub  = lane >> 4;                                         // + ks*2
    int b_row = warp_n * 32 + ((lane >> 4) & 1) * 8 + (lane & 7);  // + p*16
    int b_ub  = (lane >> 3) & 1;                                   // + ks*2
    int a_sw = a_row & 7, b_sw = b_row & 7;

    // prefetch chunk kc0/BK of tile (m0,n0) into buffer buf
    auto prefetch = [&](int m0, int n0, int ch, int buf) {
        uint32_t sb = sbase + (uint32_t)buf * 32768u;
        int kc0 = ch * BK;
#pragma unroll
        for (int it = 0; it < 4; it++) {
            int u = tid + it * 256;              // 0..1023
            int row = u >> 3;
            int kc  = u & 7;
            uint32_t sw = (uint32_t)row * 128u + (uint32_t)((kc ^ (row & 7)) << 4);
            cp_async16(sb + sw,
                       gbase + ((uint64_t)(m0 + row) * DIM + kc0 + kc * 8) * 2u);
            cp_async16(sb + 16384u + sw,
                       gbase + ((uint64_t)(n0 + row) * DIM + kc0 + kc * 8) * 2u);
        }
        CP_COMMIT();
    };

    GDC_WAIT();     // normalize complete: g_zn and g_ticket valid

    // first ticket
    if (tid == 0) s_next = atomicAdd(&g_ticket, 1);
    __syncthreads();
    int t = s_next;
    if (t >= ntri) { GDC_LAUNCH(); return; }

    int bm, bn;
    tri_decode(t, nt, bm, bn);
    int m0 = bm * 128, n0 = bn * 128;
    prefetch(m0, n0, 0, 0);

    if (tid < 128) { rowsum[tid] = 0.0f; colsum[tid] = 0.0f; }

    while (t < ntri) {
        bool diag = (bm == bn);
        bool postile = (bn - bm == btile);

        float acc[4][4][4];
#pragma unroll
        for (int mt = 0; mt < 4; mt++)
#pragma unroll
            for (int ntk = 0; ntk < 4; ntk++)
#pragma unroll
                for (int q = 0; q < 4; q++) acc[mt][ntk][q] = 0.0f;

        int t2 = ntri, bm2 = 0, bn2 = 0;

        for (int ch = 0; ch < 4; ch++) {
            int buf = ch & 1;
            bool pending;
            if (ch < 3) {
                prefetch(m0, n0, ch + 1, buf ^ 1);
                pending = true;
            } else {
                // next-tile ticket was fetched at ch==0; prefetch its chunk 0
                t2 = s_next;
                if (t2 < ntri) {
                    tri_decode(t2, nt, bm2, bn2);
                    prefetch(bm2 * 128, bn2 * 128, 0, buf ^ 1);
                    pending = true;
                } else {
                    pending = false;
                }
            }
            if (pending) { CP_WAIT(1); } else { CP_WAIT(0); }
            __syncthreads();

            if (ch == 0 && tid == 0) s_next = atomicAdd(&g_ticket, 1);

            uint32_t sA = sbase + (uint32_t)buf * 32768u;
            uint32_t sB = sA + 16384u;

#pragma unroll
            for (int ks = 0; ks < 4; ks++) {
                uint32_t ra[4][4];
#pragma unroll
                for (int mt = 0; mt < 4; mt++) {
                    int row = a_row + mt * 16;
                    int u   = ks * 2 + a_ub;
                    ldsm_x4(ra[mt], sA + row * 128 + ((u ^ a_sw) << 4));
                }
#pragma unroll
                for (int p = 0; p < 2; p++) {
                    uint32_t rb[4];
                    int row = b_row + p * 16;
                    int u   = ks * 2 + b_ub;
                    ldsm_x4(rb, sB + row * 128 + ((u ^ b_sw) << 4));
#pragma unroll
                    for (int mt = 0; mt < 4; mt++) {
                        mma16816(acc[mt][p * 2 + 0], ra[mt], rb + 0);
                        mma16816(acc[mt][p * 2 + 1], ra[mt], rb + 2);
                    }
                }
            }
            __syncthreads();
        }

        // ---------------- epilogue (next tile's chunk0 is in flight) -------
        int r0 = lane >> 2;            // 0..7
        int c0 = (lane & 3) * 2;       // 0,2,4,6

        float rs[4][2] = {};
        float cs[4][2] = {};

#pragma unroll
        for (int mt = 0; mt < 4; mt++) {
#pragma unroll
            for (int ntk = 0; ntk < 4; ntk++) {
                float e[4];
#pragma unroll
                for (int q = 0; q < 4; q++) {
                    int ml = warp_m * 64 + mt * 16 + r0 + (q >> 1) * 8;
                    int nl = warp_n * 32 + ntk * 8 + c0 + (q & 1);
                    float s = acc[mt][ntk][q];
                    if (postile && ml == nl) {
                        g_pos[m0 + ml] = s;
                        g_pos[n0 + nl] = s;
                    }
                    float v = __expf(2.0f * s);
                    if (diag && ml == nl) v = 0.0f;
                    e[q] = v;
                }
                rs[mt][0] += e[0] + e[1];
                rs[mt][1] += e[2] + e[3];
                cs[ntk][0] += e[0] + e[2];
                cs[ntk][1] += e[1] + e[3];
            }
        }
#pragma unroll
        for (int mt = 0; mt < 4; mt++)
#pragma unroll
            for (int h = 0; h < 2; h++) {
                float v = rs[mt][h];
                v += __shfl_xor_sync(0xFFFFFFFFu, v, 1);
                v += __shfl_xor_sync(0xFFFFFFFFu, v, 2);
                if ((lane & 3) == 0)
                    atomicAdd(&rowsum[warp_m * 64 + mt * 16 + r0 + h * 8], v);
            }
#pragma unroll
        for (int ntk = 0; ntk < 4; ntk++)
#pragma unroll
            for (int h = 0; h < 2; h++) {
                float v = cs[ntk][h];
                v += __shfl_xor_sync(0xFFFFFFFFu, v, 4);
                v += __shfl_xor_sync(0xFFFFFFFFu, v, 8);
                v += __shfl_xor_sync(0xFFFFFFFFu, v, 16);
                if (lane < 4)
                    atomicAdd(&colsum[warp_n * 32 + ntk * 8 + c0 + h], v);
            }
        __syncthreads();

        if (tid < 128) {
            atomicAdd(&g_denom[m0 + tid], rowsum[tid]);
            if (!diag) atomicAdd(&g_denom[n0 + tid], colsum[tid]);
            // re-zero for next tile (same threads; k-loop syncs order the rest)
            rowsum[tid] = 0.0f;
            colsum[tid] = 0.0f;
        }

        t = t2; bm = bm2; bn = bn2;
        m0 = bm * 128; n0 = bn * 128;
    }
    GDC_LAUNCH();
}

// ---------------------------------------------------------------------------
// 3) Loss: loss = log(denom) - 2*pos; block reduce + atomicAdd.
// ---------------------------------------------------------------------------
__global__ void loss_kernel(int N, float* out) {
    __shared__ float wsum[32];
    int tid  = threadIdx.x;
    int warp = tid >> 5;
    int lane = tid & 31;
    int row  = blockIdx.x * 1024 + tid;

    GDC_WAIT();

    float l = logf(g_denom[row]) - 2.0f * g_pos[row];
#pragma unroll
    for (int off = 16; off > 0; off >>= 1)
        l += __shfl_xor_sync(0xFFFFFFFF, l, off);
    if (lane == 0) wsum[warp] = l;
    __syncthreads();
    if (warp == 0) {
        float v = wsum[lane];
#pragma unroll
        for (int off = 16; off > 0; off >>= 1)
            v += __shfl_xor_sync(0xFFFFFFFF, v, off);
        if (lane == 0) atomicAdd(out, v / (float)N);
    }
}

// ---------------------------------------------------------------------------
extern "C" void kernel_launch(void* const* d_in, const int* in_sizes, int n_in,
                              void* d_out, int out_size) {
    const float* zi = (const float*)d_in[0];
    const float* zj = (const float*)d_in[1];
    int B = in_sizes[0] / DIM;     // 4096
    int N = 2 * B;                 // 8192
    int nt = N / 128;              // 64
    int ntri = nt * (nt + 1) / 2;  // 2080
    int nblk = 304;                // 2 per SM on 152 SMs
    if (nblk > ntri) nblk = ntri;

    cudaFuncSetAttribute(sim_kernel,
                         cudaFuncAttributeMaxDynamicSharedMemorySize, 65536);

    normalize_kernel<<<(N + 7) / 8, 256>>>(zi, zj, B, N, (float*)d_out);

    cudaLaunchAttribute pdl[1];
    pdl[0].id = cudaLaunchAttributeProgrammaticStreamSerialization;
    pdl[0].val.programmaticStreamSerializationAllowed = 1;

    {
        cudaLaunchConfig_t cfg = {};
        cfg.gridDim = dim3(nblk, 1, 1);
        cfg.blockDim = dim3(256, 1, 1);
        cfg.dynamicSmemBytes = 65536;
        cfg.stream = 0;
        cfg.attrs = pdl;
        cfg.numAttrs = 1;
        cudaLaunchKernelEx(&cfg, sim_kernel, nt, B / 128, ntri);
    }
    {
        cudaLaunchConfig_t cfg = {};
        cfg.gridDim = dim3(N / 1024, 1, 1);
        cfg.blockDim = dim3(1024, 1, 1);
        cfg.dynamicSmemBytes = 0;
        cfg.stream = 0;
        cfg.attrs = pdl;
        cfg.numAttrs = 1;
        cudaLaunchKernelEx(&cfg, loss_kernel, N, (float*)d_out);
    }
}

// round 17
// speedup vs baseline: 1.2341x; 1.2341x over previous
#include <cuda_runtime.h>
#include <cuda_bf16.h>
#include <math.h>
#include <stdint.h>

// NT-Xent loss, B=4096, D=256, N=8192.  bf16 HMMA Gram tiles.
// Champion configuration (R9): 65.8us, rel_err 6.3e-7.
//  1) normalize_kernel: zn = z/||z|| bf16 (1 row/warp); zeros g_denom, out.
//  2) sim_kernel: triangular 128x128 tiles of zn zn^T via mma.sync bf16.
//     256 threads, 8 warps as 2(M) x 4(N), warp tile 64x32. cp.async
//     double-buffered K loop. Epilogue: exp(2*sim), diag zeroed,
//     row sums -> g_denom[m], col sums -> g_denom[n]; positive-band tiles
//     export sim[i, i+B] to g_pos.
//  3) loss_kernel: loss = log(denom) - 2*pos, block reduce, atomicAdd.

#define DIM 256
#define MAXN 8192
#define BK 64

__device__ __nv_bfloat16 g_zn[MAXN * DIM];
__device__ float g_denom[MAXN];
__device__ float g_pos[MAXN];

__device__ __forceinline__ uint32_t smem_u32(const void* p) {
    uint32_t a;
    asm("{ .reg .u64 t; cvta.to.shared.u64 t, %1; cvt.u32.u64 %0, t; }"
        : "=r"(a) : "l"(p));
    return a;
}

__device__ __forceinline__ void ldsm_x4(uint32_t* r, uint32_t addr) {
    asm volatile("ldmatrix.sync.aligned.m8n8.x4.shared.b16 {%0,%1,%2,%3}, [%4];"
                 : "=r"(r[0]), "=r"(r[1]), "=r"(r[2]), "=r"(r[3]) : "r"(addr));
}

__device__ __forceinline__ void mma16816(float* c, const uint32_t* a,
                                         const uint32_t* b) {
    asm volatile(
        "mma.sync.aligned.m16n8k16.row.col.f32.bf16.bf16.f32 "
        "{%0,%1,%2,%3}, {%4,%5,%6,%7}, {%8,%9}, {%0,%1,%2,%3};"
        : "+f"(c[0]), "+f"(c[1]), "+f"(c[2]), "+f"(c[3])
        : "r"(a[0]), "r"(a[1]), "r"(a[2]), "r"(a[3]), "r"(b[0]), "r"(b[1]));
}

__device__ __forceinline__ void cp_async16(uint32_t saddr, uint64_t gaddr) {
    asm volatile("cp.async.cg.shared.global [%0], [%1], 16;"
                 :: "r"(saddr), "l"(gaddr) : "memory");
}
#define CP_COMMIT() asm volatile("cp.async.commit_group;" ::: "memory")
#define CP_WAIT(n)  asm volatile("cp.async.wait_group %0;" :: "n"(n) : "memory")

// ---------------------------------------------------------------------------
// 1) Normalize -> bf16 (1 row per warp); zero g_denom and out.
// ---------------------------------------------------------------------------
__global__ void normalize_kernel(const float* __restrict__ zi,
                                 const float* __restrict__ zj,
                                 int B, int N, float* out) {
    int tid  = threadIdx.x;
    int warp = tid >> 5;
    int lane = tid & 31;
    int row  = blockIdx.x * 8 + warp;

    int gtid = blockIdx.x * blockDim.x + tid;
    if (gtid < N) g_denom[gtid] = 0.0f;
    if (gtid == 0) out[0] = 0.0f;
    if (row >= N) return;

    const float* src = (row < B) ? (zi + (size_t)row * DIM)
                                 : (zj + (size_t)(row - B) * DIM);
    float4 v0 = *reinterpret_cast<const float4*>(src + lane * 8);
    float4 v1 = *reinterpret_cast<const float4*>(src + lane * 8 + 4);
    float ss = v0.x*v0.x + v0.y*v0.y + v0.z*v0.z + v0.w*v0.w
             + v1.x*v1.x + v1.y*v1.y + v1.z*v1.z + v1.w*v1.w;
#pragma unroll
    for (int off = 16; off > 0; off >>= 1)
        ss += __shfl_xor_sync(0xFFFFFFFF, ss, off);
    float inv = 1.0f / fmaxf(sqrtf(ss), 1e-8f);

    __nv_bfloat16 h[8];
    h[0] = __float2bfloat16(v0.x * inv); h[1] = __float2bfloat16(v0.y * inv);
    h[2] = __float2bfloat16(v0.z * inv); h[3] = __float2bfloat16(v0.w * inv);
    h[4] = __float2bfloat16(v1.x * inv); h[5] = __float2bfloat16(v1.y * inv);
    h[6] = __float2bfloat16(v1.z * inv); h[7] = __float2bfloat16(v1.w * inv);
    *reinterpret_cast<uint4*>(g_zn + (size_t)row * DIM + lane * 8) =
        *reinterpret_cast<uint4*>(h);
}

// ---------------------------------------------------------------------------
// 2) bf16 HMMA Gram-tile kernel. 128x128 tile per block, triangular grid
//    (bn >= bm). 256 threads: 8 warps 2(M)x4(N), warp tile 64x32.
//    K chunks of 64, cp.async double buffer, XOR-16B swizzle. Dyn smem 64KB.
// ---------------------------------------------------------------------------
__global__ __launch_bounds__(256, 2) void sim_kernel(int nt, int btile) {
    // triangular linear index -> (bm, bn), bn >= bm
    int t = blockIdx.x;
    float f = 2.0f * (float)nt + 1.0f;
    int bm = (int)((f - sqrtf(f * f - 8.0f * (float)t)) * 0.5f);
    while ((bm + 1) * nt - (((bm + 1) * bm) >> 1) <= t) bm++;
    while (bm * nt - ((bm * (bm - 1)) >> 1) > t) bm--;
    int bn = bm + (t - (bm * nt - ((bm * (bm - 1)) >> 1)));

    extern __shared__ char dsm[];
    __shared__ float rowsum[128];
    __shared__ float colsum[128];

    int tid  = threadIdx.x;
    int wid  = tid >> 5;
    int lane = tid & 31;
    int warp_m = wid & 1;      // rows 64*warp_m
    int warp_n = wid >> 1;     // cols 32*warp_n
    int m0 = bm * 128, n0 = bn * 128;
    bool diag = (bm == bn);
    bool postile = (bn - bm == btile);

    if (tid < 128) { rowsum[tid] = 0.0f; colsum[tid] = 0.0f; }

    uint32_t sbase = smem_u32(dsm);
    uint64_t gbase = (uint64_t)__cvta_generic_to_global(g_zn);

    float acc[4][4][4];        // [mt 16-row][ntk 8-col][quad]
#pragma unroll
    for (int mt = 0; mt < 4; mt++)
#pragma unroll
        for (int ntk = 0; ntk < 4; ntk++)
#pragma unroll
            for (int q = 0; q < 4; q++) acc[mt][ntk][q] = 0.0f;

    int a_row = warp_m * 64 + (lane & 15);                         // + mt*16
    int a_ub  = lane >> 4;                                         // + ks*2
    int b_row = warp_n * 32 + ((lane >> 4) & 1) * 8 + (lane & 7);  // + p*16
    int b_ub  = (lane >> 3) & 1;                                   // + ks*2
    int a_sw = a_row & 7, b_sw = b_row & 7;

    auto prefetch = [&](int ch, int buf) {
        uint32_t sb = sbase + (uint32_t)buf * 32768u;
        int kc0 = ch * BK;
#pragma unroll
        for (int it = 0; it < 4; it++) {
            int u = tid + it * 256;              // 0..1023
            int row = u >> 3;
            int kc  = u & 7;
            uint32_t sw = (uint32_t)row * 128u + (uint32_t)((kc ^ (row & 7)) << 4);
            cp_async16(sb + sw,
                       gbase + ((uint64_t)(m0 + row) * DIM + kc0 + kc * 8) * 2u);
            cp_async16(sb + 16384u + sw,
                       gbase + ((uint64_t)(n0 + row) * DIM + kc0 + kc * 8) * 2u);
        }
        CP_COMMIT();
    };

    prefetch(0, 0);

    for (int ch = 0; ch < 4; ch++) {
        int buf = ch & 1;
        if (ch + 1 < 4) {
            prefetch(ch + 1, (ch + 1) & 1);
            CP_WAIT(1);
        } else {
            CP_WAIT(0);
        }
        __syncthreads();

        uint32_t sA = sbase + (uint32_t)buf * 32768u;
        uint32_t sB = sA + 16384u;

#pragma unroll
        for (int ks = 0; ks < 4; ks++) {
            uint32_t ra[4][4];
#pragma unroll
            for (int mt = 0; mt < 4; mt++) {
                int row = a_row + mt * 16;
                int u   = ks * 2 + a_ub;
                ldsm_x4(ra[mt], sA + row * 128 + ((u ^ a_sw) << 4));
            }
#pragma unroll
            for (int p = 0; p < 2; p++) {
                uint32_t rb[4];
                int row = b_row + p * 16;
                int u   = ks * 2 + b_ub;
                ldsm_x4(rb, sB + row * 128 + ((u ^ b_sw) << 4));
#pragma unroll
                for (int mt = 0; mt < 4; mt++) {
                    mma16816(acc[mt][p * 2 + 0], ra[mt], rb + 0);
                    mma16816(acc[mt][p * 2 + 1], ra[mt], rb + 2);
                }
            }
        }
        __syncthreads();
    }

    // ---------------- epilogue ----------------
    int r0 = lane >> 2;            // 0..7
    int c0 = (lane & 3) * 2;       // 0,2,4,6

    float rs[4][2] = {};           // [mt][row half]
    float cs[4][2] = {};           // [ntk][col pair]

#pragma unroll
    for (int mt = 0; mt < 4; mt++) {
#pragma unroll
        for (int ntk = 0; ntk < 4; ntk++) {
            float e[4];
#pragma unroll
            for (int q = 0; q < 4; q++) {
                int ml = warp_m * 64 + mt * 16 + r0 + (q >> 1) * 8;
                int nl = warp_n * 32 + ntk * 8 + c0 + (q & 1);
                float s = acc[mt][ntk][q];
                if (postile && ml == nl) {
                    g_pos[m0 + ml] = s;
                    g_pos[n0 + nl] = s;
                }
                float v = __expf(2.0f * s);
                if (diag && ml == nl) v = 0.0f;
                e[q] = v;
            }
            rs[mt][0] += e[0] + e[1];
            rs[mt][1] += e[2] + e[3];
            cs[ntk][0] += e[0] + e[2];
            cs[ntk][1] += e[1] + e[3];
        }
    }
#pragma unroll
    for (int mt = 0; mt < 4; mt++)
#pragma unroll
        for (int h = 0; h < 2; h++) {
            float v = rs[mt][h];
            v += __shfl_xor_sync(0xFFFFFFFFu, v, 1);
            v += __shfl_xor_sync(0xFFFFFFFFu, v, 2);
            if ((lane & 3) == 0)
                atomicAdd(&rowsum[warp_m * 64 + mt * 16 + r0 + h * 8], v);
        }
#pragma unroll
    for (int ntk = 0; ntk < 4; ntk++)
#pragma unroll
        for (int h = 0; h < 2; h++) {
            float v = cs[ntk][h];
            v += __shfl_xor_sync(0xFFFFFFFFu, v, 4);
            v += __shfl_xor_sync(0xFFFFFFFFu, v, 8);
            v += __shfl_xor_sync(0xFFFFFFFFu, v, 16);
            if (lane < 4)
                atomicAdd(&colsum[warp_n * 32 + ntk * 8 + c0 + h], v);
        }
    __syncthreads();

    if (tid < 128) {
        atomicAdd(&g_denom[m0 + tid], rowsum[tid]);
        if (!diag) atomicAdd(&g_denom[n0 + tid], colsum[tid]);
    }
}

// ---------------------------------------------------------------------------
// 3) Loss + reduction from g_denom / g_pos only.
// ---------------------------------------------------------------------------
__global__ void loss_kernel(int N, float* out) {
    __shared__ float wsum[32];
    int tid  = threadIdx.x;
    int warp = tid >> 5;
    int lane = tid & 31;
    int row  = blockIdx.x * 1024 + tid;

    float l = logf(g_denom[row]) - 2.0f * g_pos[row];
#pragma unroll
    for (int off = 16; off > 0; off >>= 1)
        l += __shfl_xor_sync(0xFFFFFFFF, l, off);
    if (lane == 0) wsum[warp] = l;
    __syncthreads();
    if (warp == 0) {
        float v = wsum[lane];
#pragma unroll
        for (int off = 16; off > 0; off >>= 1)
            v += __shfl_xor_sync(0xFFFFFFFF, v, off);
        if (lane == 0) atomicAdd(out, v / (float)N);
    }
}

// ---------------------------------------------------------------------------
extern "C" void kernel_launch(void* const* d_in, const int* in_sizes, int n_in,
                              void* d_out, int out_size) {
    const float* zi = (const float*)d_in[0];
    const float* zj = (const float*)d_in[1];
    int B = in_sizes[0] / DIM;     // 4096
    int N = 2 * B;                 // 8192
    int nt = N / 128;              // 64
    int ntri = nt * (nt + 1) / 2;  // 2080

    cudaFuncSetAttribute(sim_kernel,
                         cudaFuncAttributeMaxDynamicSharedMemorySize, 65536);

    normalize_kernel<<<(N + 7) / 8, 256>>>(zi, zj, B, N, (float*)d_out);
    sim_kernel<<<ntri, 256, 65536>>>(nt, B / 128);
    loss_kernel<<<N / 1024, 1024>>>(N, (float*)d_out);
}